// round 3
// baseline (speedup 1.0000x reference)
#include <cuda_runtime.h>

#define S_LEN    2048
#define NBATCH   64
#define DIN      512
#define HDIM     512
#define NCTA     128
#define NTHREADS 256
#define KT       64
#define ASTRIDE  68            // 64 + 4 pad
#define ABUF     (64 * ASTRIDE)
#define NROWS    16            // gate rows per CTA (4 units x 4 gates)
#define KTOT     1024          // DIN + HDIM

// Software grid barrier state (persists across graph replays; gen0-relative)
__device__ unsigned g_bar_count = 0;
__device__ unsigned g_bar_gen   = 0;

__device__ __forceinline__ float fast_sigmoid(float x) {
    return 1.0f / (1.0f + __expf(-x));
}
__device__ __forceinline__ float fast_tanh(float x) {
    float ax = fabsf(x);
    float e  = __expf(-2.0f * ax);
    float t  = (1.0f - e) / (1.0f + e);
    return copysignf(t, x);
}

// packed dual-FMA: d.lo += a.lo*b.lo ; d.hi += a.hi*b.hi
__device__ __forceinline__ void ffma2(unsigned long long& d,
                                      unsigned long long a,
                                      unsigned long long b) {
    asm("fma.rn.f32x2 %0, %1, %2, %0;" : "+l"(d) : "l"(a), "l"(b));
}
__device__ __forceinline__ float pairsum(unsigned long long v) {
    float lo, hi;
    asm("mov.b64 {%0, %1}, %2;" : "=f"(lo), "=f"(hi) : "l"(v));
    return lo + hi;
}

__global__ __launch_bounds__(NTHREADS)
void lstm_persistent(const float* __restrict__ x,
                     const float* __restrict__ Wih,
                     const float* __restrict__ Whh,
                     const float* __restrict__ bih,
                     const float* __restrict__ bhh,
                     float* __restrict__ out)
{
    extern __shared__ float sm[];
    // Wsm2: paired weights, ull[(kp)*16 + r] = (W[2kp][r], W[2kp+1][r]); 64 KB
    unsigned long long* Wsm2 = (unsigned long long*)sm;
    float* As  = sm + (KTOT / 2) * NROWS * 2;   // 2 x [64 * ASTRIDE]  34 KB
    float* Red = As;                            // aliases As (8K floats needed)
    float* bsm = As + 2 * ABUF;                 // [NROWS]

    const int tid = threadIdx.x;
    const int ct  = blockIdx.x;

    // GEMM mapping: tid = ks*32 + rg*8 + bg
    //   thread owns batches {j*8+bg}, rows rg*4..rg*4+3, k-slice ks (8 k / tile)
    const int bg = tid & 7;
    const int rg = (tid >> 3) & 3;
    const int ks = tid >> 5;

    // Staging loader mapping
    const int lb = tid >> 2;
    const int kc = (tid & 3) * 4;

    // Elementwise mapping: (batch eb, local unit eu); c stays in a register
    const int eb = tid >> 2;
    const int eu = tid & 3;
    float c_state = 0.0f;

    // ---- persistent weight slice -> SMEM (paired layout) ----
    // local row r = unit*4 + gate  ->  global W row = gate*HDIM + ct*4 + unit
    for (int idx = tid; idx < NROWS * KTOT; idx += NTHREADS) {
        int r = idx >> 10;
        int k = idx & (KTOT - 1);
        int unit = r >> 2, gate = r & 3;
        int grow = gate * HDIM + ct * 4 + unit;
        float w = (k < DIN) ? Wih[grow * DIN + k] : Whh[grow * HDIM + (k - DIN)];
        ((float*)Wsm2)[(((k >> 1) * NROWS + r) << 1) | (k & 1)] = w;
    }
    if (tid < NROWS) {
        int unit = tid >> 2, gate = tid & 3;
        int grow = gate * HDIM + ct * 4 + unit;
        bsm[tid] = bih[grow] + bhh[grow];
    }

    unsigned gen0 = 0;
    if (tid == 0) gen0 = *((volatile unsigned*)&g_bar_gen);

    float* hout = out;
    float* cout = out + (size_t)S_LEN * NBATCH * HDIM;

    __syncthreads();

    for (int t = 0; t < S_LEN; ++t) {
        unsigned long long acc[8][4];
#pragma unroll
        for (int j = 0; j < 8; ++j)
#pragma unroll
            for (int r = 0; r < 4; ++r) acc[j][r] = 0ull;

        const int nTiles = (t == 0) ? 8 : 16;      // t=0: h phase all zeros
        const float* xbase = x + (size_t)t * NBATCH * DIN;
        const float* hbase = hout + (size_t)(t - 1) * NBATCH * HDIM;

        float4 ld0, ld1, ld2, ld3;

#define LOADT(TILE) do {                                                  \
            int _ph = (TILE) >> 3;                                        \
            int _kt = ((TILE) & 7) * KT;                                  \
            const float* _p = ((_ph == 0) ? xbase : hbase)                \
                              + (size_t)lb * 512 + _kt + kc;              \
            ld0 = *(const float4*)(_p);                                   \
            ld1 = *(const float4*)(_p + 16);                              \
            ld2 = *(const float4*)(_p + 32);                              \
            ld3 = *(const float4*)(_p + 48);                              \
        } while (0)
#define STORET(BUF) do {                                                  \
            float* _d = As + (BUF) * ABUF + lb * ASTRIDE + kc;            \
            *(float4*)(_d)      = ld0;                                    \
            *(float4*)(_d + 16) = ld1;                                    \
            *(float4*)(_d + 32) = ld2;                                    \
            *(float4*)(_d + 48) = ld3;                                    \
        } while (0)

        LOADT(0);
        STORET(0);
        __syncthreads();

        for (int tile = 0; tile < nTiles; ++tile) {
            const int cur = tile & 1;
            const bool more = (tile + 1 < nTiles);
            if (more) LOADT(tile + 1);

            const float* Abuf = As + cur * ABUF;
            const int kpb = tile * (KT / 2);       // global k-pair base

#pragma unroll
            for (int c = 0; c < 2; ++c) {
                const int kof = ks * 8 + c * 4;    // k offset in tile
                ulonglong2 av[8];
#pragma unroll
                for (int j = 0; j < 8; ++j)
                    av[j] = *(const ulonglong2*)(Abuf + (j * 8 + bg) * ASTRIDE + kof);

                const unsigned long long* wp =
                    Wsm2 + (size_t)(kpb + (kof >> 1)) * NROWS + rg * 4;
                ulonglong2 w00 = *(const ulonglong2*)(wp);        // kp0, rows r0,r1
                ulonglong2 w01 = *(const ulonglong2*)(wp + 2);    // kp0, rows r2,r3
                ulonglong2 w10 = *(const ulonglong2*)(wp + 16);   // kp1, rows r0,r1
                ulonglong2 w11 = *(const ulonglong2*)(wp + 18);   // kp1, rows r2,r3

#pragma unroll
                for (int j = 0; j < 8; ++j) {
                    ffma2(acc[j][0], av[j].x, w00.x);
                    ffma2(acc[j][1], av[j].x, w00.y);
                    ffma2(acc[j][2], av[j].x, w01.x);
                    ffma2(acc[j][3], av[j].x, w01.y);
                }
#pragma unroll
                for (int j = 0; j < 8; ++j) {
                    ffma2(acc[j][0], av[j].y, w10.x);
                    ffma2(acc[j][1], av[j].y, w10.y);
                    ffma2(acc[j][2], av[j].y, w11.x);
                    ffma2(acc[j][3], av[j].y, w11.y);
                }
            }

            if (more) STORET(cur ^ 1);
            __syncthreads();
        }
#undef LOADT
#undef STORET

        // ---- k-split reduction: partials -> Red[ks][b*16 + r] ----
#pragma unroll
        for (int j = 0; j < 8; ++j) {
            float4 v;
            v.x = pairsum(acc[j][0]);
            v.y = pairsum(acc[j][1]);
            v.z = pairsum(acc[j][2]);
            v.w = pairsum(acc[j][3]);
            *(float4*)(Red + ks * 1024 + (j * 8 + bg) * 16 + rg * 4) = v;
        }
        __syncthreads();

        float4 g = make_float4(0.f, 0.f, 0.f, 0.f);
#pragma unroll
        for (int k2 = 0; k2 < 8; ++k2) {
            float4 p = *(const float4*)(Red + k2 * 1024 + 4 * tid);
            g.x += p.x; g.y += p.y; g.z += p.z; g.w += p.w;
        }

        float gi = fast_sigmoid(g.x + bsm[eu * 4 + 0]);
        float gf = fast_sigmoid(g.y + bsm[eu * 4 + 1]);
        float gg = fast_tanh  (g.z + bsm[eu * 4 + 2]);
        float go = fast_sigmoid(g.w + bsm[eu * 4 + 3]);
        c_state = gf * c_state + gi * gg;
        float hval = go * fast_tanh(c_state);

        size_t o = (size_t)t * NBATCH * HDIM + (size_t)eb * HDIM + ct * 4 + eu;
        hout[o] = hval;
        cout[o] = c_state;

        // ---- grid barrier: h_t globally visible before step t+1 ----
        __threadfence();
        __syncthreads();
        if (tid == 0) {
            unsigned target = gen0 + (unsigned)t + 1u;
            unsigned old = atomicAdd(&g_bar_count, 1u);
            if (old == (unsigned)(NCTA - 1)) {
                atomicExch(&g_bar_count, 0u);
                __threadfence();
                atomicAdd(&g_bar_gen, 1u);
            } else {
                while ((int)(*((volatile unsigned*)&g_bar_gen) - target) < 0) { }
            }
        }
        __syncthreads();
    }
}

extern "C" void kernel_launch(void* const* d_in, const int* in_sizes, int n_in,
                              void* d_out, int out_size)
{
    const float* x   = (const float*)d_in[0];
    const float* Wih = (const float*)d_in[1];
    const float* Whh = (const float*)d_in[2];
    const float* bih = (const float*)d_in[3];
    const float* bhh = (const float*)d_in[4];
    float* out = (float*)d_out;

    // ~100.4 KB used; request 132 KB to force 1 CTA/SM so the 128-CTA
    // persistent grid is fully co-resident (software barrier deadlock-free).
    const int smem_bytes = 132 * 1024;
    cudaFuncSetAttribute(lstm_persistent,
                         cudaFuncAttributeMaxDynamicSharedMemorySize, smem_bytes);

    lstm_persistent<<<NCTA, NTHREADS, smem_bytes>>>(x, Wih, Whh, bih, bhh, out);
}

// round 4
// speedup vs baseline: 1.4545x; 1.4545x over previous
#include <cuda_runtime.h>

#define S_LEN    2048
#define NBATCH   64
#define DIN      512
#define HDIM     512
#define NCTA     128
#define NTHREADS 512
#define KT       64
#define ASTRIDE  68            // 64 + 4 pad
#define ABUF     (64 * ASTRIDE)
#define NROWS    16            // gate rows per CTA (4 units x 4 gates)
#define KTOT     1024          // DIN + HDIM

// Software grid barrier state (persists across graph replays; gen0-relative)
__device__ unsigned g_bar_count = 0;
__device__ unsigned g_bar_gen   = 0;

__device__ __forceinline__ float fast_sigmoid(float x) {
    return 1.0f / (1.0f + __expf(-x));
}
__device__ __forceinline__ float fast_tanh(float x) {
    float ax = fabsf(x);
    float e  = __expf(-2.0f * ax);
    float t  = (1.0f - e) / (1.0f + e);
    return copysignf(t, x);
}

// packed dual-FMA: d.lo += a.lo*b.lo ; d.hi += a.hi*b.hi
__device__ __forceinline__ void ffma2(unsigned long long& d,
                                      unsigned long long a,
                                      unsigned long long b) {
    asm("fma.rn.f32x2 %0, %1, %2, %0;" : "+l"(d) : "l"(a), "l"(b));
}
__device__ __forceinline__ float pairsum(unsigned long long v) {
    float lo, hi;
    asm("mov.b64 {%0, %1}, %2;" : "=f"(lo), "=f"(hi) : "l"(v));
    return lo + hi;
}

__global__ __launch_bounds__(NTHREADS, 1)
void lstm_persistent(const float* __restrict__ x,
                     const float* __restrict__ Wih,
                     const float* __restrict__ Whh,
                     const float* __restrict__ bih,
                     const float* __restrict__ bhh,
                     float* __restrict__ out)
{
    extern __shared__ float sm[];
    // Wsm2: paired weights, ull[kp*16 + r] = (W[2kp][r], W[2kp+1][r]); 64 KB
    unsigned long long* Wsm2 = (unsigned long long*)sm;
    float* As   = sm + (KTOT / 2) * NROWS * 2;   // 4 x ABUF  (~69.6 KB)
    float* bsm  = As + 4 * ABUF;                 // [NROWS]
    unsigned* sgen0 = (unsigned*)(bsm + NROWS);

    const int tid = threadIdx.x;
    const int ct  = blockIdx.x;
    const int hid = tid >> 8;       // 0 = x half (warps 0-7), 1 = h half
    const int ht  = tid & 255;

    // GEMM mapping within a half: batches {j*16+bg}, rows rg*4..+3, k-slice ks
    const int bg = ht & 15;
    const int rg = (ht >> 4) & 3;
    const int ks = ht >> 6;         // 0..3, 16 k per tile each

    // Staging loader mapping (within half)
    const int lb = ht >> 2;
    const int kc = (ht & 3) * 4;

    // Elementwise mapping (low 256 threads): (batch eb, local unit eu)
    const int eb = tid >> 2;
    const int eu = tid & 3;
    float c_state = 0.0f;

    float* Ah   = As + hid * 2 * ABUF;   // this half's double buffer
    float* RedA = As;                    // 4 slices x 1024 floats (aliases bufs)
    float* RedB = As + 2 * ABUF;

    // ---- persistent weight slice -> SMEM (paired layout) ----
    for (int idx = tid; idx < NROWS * KTOT; idx += NTHREADS) {
        int r = idx >> 10;
        int k = idx & (KTOT - 1);
        int unit = r >> 2, gate = r & 3;
        int grow = gate * HDIM + ct * 4 + unit;
        float w = (k < DIN) ? Wih[grow * DIN + k] : Whh[grow * HDIM + (k - DIN)];
        ((float*)Wsm2)[(((k >> 1) * NROWS + r) << 1) | (k & 1)] = w;
    }
    if (tid < NROWS) {
        int unit = tid >> 2, gate = tid & 3;
        int grow = gate * HDIM + ct * 4 + unit;
        bsm[tid] = bih[grow] + bhh[grow];
    }
    if (tid == 0) *sgen0 = *((volatile unsigned*)&g_bar_gen);
    __syncthreads();
    const unsigned gen0 = *sgen0;

    float* hout = out;
    float* cout = out + (size_t)S_LEN * NBATCH * HDIM;

    for (int t = 0; t < S_LEN; ++t) {
        float* Red = hid ? RedB : RedA;

        if (hid == 1 && t == 0) {
            // h0 == 0: zero partials, no compute, no wait
            float4 z = make_float4(0.f, 0.f, 0.f, 0.f);
            for (int i = ht; i < 1024; i += 256)
                *(float4*)(RedB + 4 * i) = z;
        } else {
            if (hid == 1) {
                // split-phase grid barrier: WAIT here (overlapped with x half)
                if (ht == 0) {
                    unsigned target = gen0 + (unsigned)t;
                    while ((int)(*((volatile unsigned*)&g_bar_gen) - target) < 0) { }
                }
                asm volatile("bar.sync 2, 256;" ::: "memory");
            }
            const float* srcb = (hid == 0)
                ? x + (size_t)t * NBATCH * DIN
                : hout + (size_t)(t - 1) * NBATCH * HDIM;

            unsigned long long acc[4][4];
#pragma unroll
            for (int j = 0; j < 4; ++j)
#pragma unroll
                for (int r = 0; r < 4; ++r) acc[j][r] = 0ull;

            float4 ld0, ld1, ld2, ld3;

#define LOADT(TILE) do {                                                  \
                const float* _p = srcb + (size_t)lb * 512 + (TILE)*KT + kc; \
                ld0 = *(const float4*)(_p);                               \
                ld1 = *(const float4*)(_p + 16);                          \
                ld2 = *(const float4*)(_p + 32);                          \
                ld3 = *(const float4*)(_p + 48);                          \
            } while (0)
#define STORET(BUF) do {                                                  \
                float* _d = Ah + (BUF) * ABUF + lb * ASTRIDE + kc;        \
                *(float4*)(_d)      = ld0;                                \
                *(float4*)(_d + 16) = ld1;                                \
                *(float4*)(_d + 32) = ld2;                                \
                *(float4*)(_d + 48) = ld3;                                \
            } while (0)

            LOADT(0);
            STORET(0);
            asm volatile("bar.sync %0, 256;" :: "r"(hid + 1) : "memory");

            for (int tile = 0; tile < 8; ++tile) {
                const int cur = tile & 1;
                const bool more = (tile + 1 < 8);
                if (more) LOADT(tile + 1);

                const float* Abuf = Ah + cur * ABUF;
                const int kpb = (hid * 512 + tile * KT) >> 1;  // k-pair base

#pragma unroll
                for (int c = 0; c < 4; ++c) {
                    const int kof = ks * 16 + c * 4;
                    const unsigned long long* wp =
                        Wsm2 + (size_t)(kpb + (kof >> 1)) * NROWS + rg * 4;
                    ulonglong2 w00 = *(const ulonglong2*)(wp);       // kp0 r0,r1
                    ulonglong2 w01 = *(const ulonglong2*)(wp + 2);   // kp0 r2,r3
                    ulonglong2 w10 = *(const ulonglong2*)(wp + 16);  // kp1 r0,r1
                    ulonglong2 w11 = *(const ulonglong2*)(wp + 18);  // kp1 r2,r3

#pragma unroll
                    for (int j = 0; j < 4; ++j) {
                        ulonglong2 av =
                            *(const ulonglong2*)(Abuf + (j * 16 + bg) * ASTRIDE + kof);
                        ffma2(acc[j][0], av.x, w00.x);
                        ffma2(acc[j][1], av.x, w00.y);
                        ffma2(acc[j][2], av.x, w01.x);
                        ffma2(acc[j][3], av.x, w01.y);
                        ffma2(acc[j][0], av.y, w10.x);
                        ffma2(acc[j][1], av.y, w10.y);
                        ffma2(acc[j][2], av.y, w11.x);
                        ffma2(acc[j][3], av.y, w11.y);
                    }
                }

                if (more) STORET(cur ^ 1);
                asm volatile("bar.sync %0, 256;" :: "r"(hid + 1) : "memory");
            }
#undef LOADT
#undef STORET

            // partials -> Red[ks][b*16 + r] (aliases this half's buf0, done reading)
#pragma unroll
            for (int j = 0; j < 4; ++j) {
                float4 v;
                v.x = pairsum(acc[j][0]);
                v.y = pairsum(acc[j][1]);
                v.z = pairsum(acc[j][2]);
                v.w = pairsum(acc[j][3]);
                *(float4*)(Red + ks * 1024 + (j * 16 + bg) * 16 + rg * 4) = v;
            }
        }

        __syncthreads();   // both halves' partials ready

        if (tid < 256) {
            float4 g = make_float4(0.f, 0.f, 0.f, 0.f);
#pragma unroll
            for (int s = 0; s < 4; ++s) {
                float4 p = *(const float4*)(RedA + s * 1024 + 4 * tid);
                g.x += p.x; g.y += p.y; g.z += p.z; g.w += p.w;
                float4 q = *(const float4*)(RedB + s * 1024 + 4 * tid);
                g.x += q.x; g.y += q.y; g.z += q.z; g.w += q.w;
            }

            float gi = fast_sigmoid(g.x + bsm[eu * 4 + 0]);
            float gf = fast_sigmoid(g.y + bsm[eu * 4 + 1]);
            float gg = fast_tanh  (g.z + bsm[eu * 4 + 2]);
            float go = fast_sigmoid(g.w + bsm[eu * 4 + 3]);
            c_state = gf * c_state + gi * gg;
            float hval = go * fast_tanh(c_state);

            size_t o = (size_t)t * NBATCH * HDIM + (size_t)eb * HDIM + ct * 4 + eu;
            hout[o] = hval;
            cout[o] = c_state;
            __threadfence();
        }

        __syncthreads();   // h_t written + fenced by all writers

        // arrive-only; the wait lives in the h-half of step t+1
        if (tid == 0) {
            unsigned old = atomicAdd(&g_bar_count, 1u);
            if (old == (unsigned)(NCTA - 1)) {
                atomicExch(&g_bar_count, 0u);
                __threadfence();
                atomicAdd(&g_bar_gen, 1u);
            }
        }
    }
}

extern "C" void kernel_launch(void* const* d_in, const int* in_sizes, int n_in,
                              void* d_out, int out_size)
{
    const float* x   = (const float*)d_in[0];
    const float* Wih = (const float*)d_in[1];
    const float* Whh = (const float*)d_in[2];
    const float* bih = (const float*)d_in[3];
    const float* bhh = (const float*)d_in[4];
    float* out = (float*)d_out;

    // 64KB weights + 4x17.4KB A/Red + misc  (~135 KB): >114KB -> 1 CTA/SM,
    // so the 128-CTA persistent grid is fully co-resident (barrier safe).
    const int smem_bytes = ((KTOT / 2) * NROWS * 2 + 4 * ABUF + NROWS + 16) * 4;
    cudaFuncSetAttribute(lstm_persistent,
                         cudaFuncAttributeMaxDynamicSharedMemorySize, smem_bytes);

    lstm_persistent<<<NCTA, NTHREADS, smem_bytes>>>(x, Wih, Whh, bih, bhh, out);
}